// round 7
// baseline (speedup 1.0000x reference)
#include <cuda_runtime.h>
#include <cuda_bf16.h>
#include <cstddef>
#include <cstdint>

// Problem constants
#define BATCH 4
#define SEQ   2048
#define DIM   1024
#define HEADS 16
#define DH    64
#define MROWS (BATCH*SEQ)  // 8192
#define SCALE 0.03125f     // 1/sqrt(1024)

// Scratch (allocation-free rule: __device__ globals)
__device__ float g_Q[(size_t)MROWS * DIM];
__device__ float g_K[(size_t)MROWS * DIM];
__device__ float g_V[(size_t)MROWS * DIM];
__device__ float g_C[(size_t)MROWS * DIM];

// ---------------------------------------------------------------------------
// TF32 mma.sync GEMM: C[M,N] = A[M,K] * B[K,N], row-major, fp32 in/out.
// 128x128x16 block tile, 256 threads (8 warps, 4x2), warp tile 32x64.
// (tcgen05 unavailable: harness compiles PTX at .target sm_103, not sm_103a)
// ---------------------------------------------------------------------------
#define BM 128
#define BN 128
#define BK 16
#define SA_STR 20
#define SB_STR 136

__device__ __forceinline__ float to_tf32(float x) {
    float r;
    asm("cvt.rna.tf32.f32 %0, %1;" : "=f"(r) : "f"(x));
    return r;
}

__device__ __forceinline__ void mma_tf32(float* c, const uint32_t* a, const uint32_t* b) {
    asm volatile(
        "mma.sync.aligned.m16n8k8.row.col.f32.tf32.tf32.f32 "
        "{%0,%1,%2,%3}, {%4,%5,%6,%7}, {%8,%9}, {%0,%1,%2,%3};"
        : "+f"(c[0]), "+f"(c[1]), "+f"(c[2]), "+f"(c[3])
        : "r"(a[0]), "r"(a[1]), "r"(a[2]), "r"(a[3]), "r"(b[0]), "r"(b[1]));
}

__global__ __launch_bounds__(256) void gemm_tf32(const float* __restrict__ A,
                                                 const float* __restrict__ B,
                                                 float* __restrict__ C,
                                                 int M, int N, int K) {
    __shared__ float sA[BM * SA_STR];
    __shared__ float sB[BK * SB_STR];

    int tid  = threadIdx.x;
    int lane = tid & 31;
    int warp = tid >> 5;
    int gr = lane >> 2;
    int tq = lane & 3;
    int wm = (warp & 3) * 32;
    int wn = (warp >> 2) * 64;

    int bx = blockIdx.x, by = blockIdx.y;

    int a_row1 = tid >> 2;
    int a_kc   = (tid & 3) * 4;
    int b_kr   = tid >> 5;
    int b_nc   = (tid & 31) * 4;

    const float* Ap = A + (size_t)(by * BM + a_row1) * K + a_kc;
    const float* Bp = B + (size_t)b_kr * N + bx * BN + b_nc;

    float acc[2][8][4];
#pragma unroll
    for (int mt = 0; mt < 2; mt++)
#pragma unroll
        for (int nt = 0; nt < 8; nt++)
#pragma unroll
            for (int i = 0; i < 4; i++) acc[mt][nt][i] = 0.f;

    float4 ra0 = *(const float4*)(Ap);
    float4 ra1 = *(const float4*)(Ap + (size_t)64 * K);
    float4 rb0 = *(const float4*)(Bp);
    float4 rb1 = *(const float4*)(Bp + (size_t)8 * N);

    for (int k0 = 0; k0 < K; k0 += BK) {
        __syncthreads();
        {
            float4 t;
            t.x = to_tf32(ra0.x); t.y = to_tf32(ra0.y); t.z = to_tf32(ra0.z); t.w = to_tf32(ra0.w);
            *(float4*)&sA[a_row1 * SA_STR + a_kc] = t;
            t.x = to_tf32(ra1.x); t.y = to_tf32(ra1.y); t.z = to_tf32(ra1.z); t.w = to_tf32(ra1.w);
            *(float4*)&sA[(a_row1 + 64) * SA_STR + a_kc] = t;
            t.x = to_tf32(rb0.x); t.y = to_tf32(rb0.y); t.z = to_tf32(rb0.z); t.w = to_tf32(rb0.w);
            *(float4*)&sB[b_kr * SB_STR + b_nc] = t;
            t.x = to_tf32(rb1.x); t.y = to_tf32(rb1.y); t.z = to_tf32(rb1.z); t.w = to_tf32(rb1.w);
            *(float4*)&sB[(b_kr + 8) * SB_STR + b_nc] = t;
        }
        __syncthreads();

        if (k0 + BK < K) {
            Ap += BK;
            Bp += (size_t)BK * N;
            ra0 = *(const float4*)(Ap);
            ra1 = *(const float4*)(Ap + (size_t)64 * K);
            rb0 = *(const float4*)(Bp);
            rb1 = *(const float4*)(Bp + (size_t)8 * N);
        }

#pragma unroll
        for (int kt = 0; kt < BK; kt += 8) {
            uint32_t af[2][4];
            uint32_t bf[8][2];
#pragma unroll
            for (int mt = 0; mt < 2; mt++) {
                int base = (wm + mt * 16 + gr) * SA_STR + kt + tq;
                af[mt][0] = __float_as_uint(sA[base]);
                af[mt][1] = __float_as_uint(sA[base + 8 * SA_STR]);
                af[mt][2] = __float_as_uint(sA[base + 4]);
                af[mt][3] = __float_as_uint(sA[base + 8 * SA_STR + 4]);
            }
#pragma unroll
            for (int nt = 0; nt < 8; nt++) {
                int nb = wn + nt * 8 + gr;
                bf[nt][0] = __float_as_uint(sB[(kt + tq) * SB_STR + nb]);
                bf[nt][1] = __float_as_uint(sB[(kt + tq + 4) * SB_STR + nb]);
            }
#pragma unroll
            for (int mt = 0; mt < 2; mt++)
#pragma unroll
                for (int nt = 0; nt < 8; nt++)
                    mma_tf32(acc[mt][nt], af[mt], bf[nt]);
        }
    }

#pragma unroll
    for (int mt = 0; mt < 2; mt++) {
#pragma unroll
        for (int nt = 0; nt < 8; nt++) {
            int row = by * BM + wm + mt * 16 + gr;
            int col = bx * BN + wn + nt * 8 + 2 * tq;
            *(float2*)&C[(size_t)row * N + col] =
                make_float2(acc[mt][nt][0], acc[mt][nt][1]);
            *(float2*)&C[(size_t)(row + 8) * N + col] =
                make_float2(acc[mt][nt][2], acc[mt][nt][3]);
        }
    }
}

// ---------------------------------------------------------------------------
// Flash attention, 2 threads per query row (32 head-dims each), float4 LDS.
// 256 threads = 128 queries per block. grid = (SEQ/128, HEADS, BATCH).
// Partner lanes (t, t^1) hold the two halves; one shfl_xor completes the dot.
// ---------------------------------------------------------------------------
#define KT 16
#define DHALF 32

__global__ __launch_bounds__(256, 2) void attn_kernel(const float* __restrict__ Q,
                                                      const float* __restrict__ K,
                                                      const float* __restrict__ V,
                                                      float* __restrict__ O) {
    __shared__ float sK[KT][DH];
    __shared__ float sV[KT][DH];

    int b = blockIdx.z;
    int h = blockIdx.y;
    int t = threadIdx.x;
    int qi   = t >> 1;          // 0..127
    int d0   = (t & 1) * DHALF; // 0 or 32
    int qrow = blockIdx.x * 128 + qi;

    const float* qp = Q + ((size_t)(b * SEQ + qrow)) * DIM + h * DH + d0;
    float q[DHALF], o[DHALF];
#pragma unroll
    for (int i = 0; i < DHALF / 4; i++) {
        float4 v4 = ((const float4*)qp)[i];
        q[4*i+0] = v4.x; q[4*i+1] = v4.y; q[4*i+2] = v4.z; q[4*i+3] = v4.w;
    }
#pragma unroll
    for (int d = 0; d < DHALF; d++) o[d] = 0.f;

    float m = -1e30f, l = 0.f;
    const size_t kbase = (size_t)b * SEQ * DIM + (size_t)h * DH;

    // staging: 256 float4 slots each for K and V; thread t owns slot t
    int sr  = t >> 4;            // 0..15
    int sc4 = t & 15;            // 0..15

    for (int k0 = 0; k0 < SEQ; k0 += KT) {
        size_t rowoff = kbase + (size_t)(k0 + sr) * DIM;
        float4 kk = *((const float4*)(K + rowoff) + sc4);
        float4 vv = *((const float4*)(V + rowoff) + sc4);
        __syncthreads();
        ((float4*)&sK[sr][0])[sc4] = kk;
        ((float4*)&sV[sr][0])[sc4] = vv;
        __syncthreads();

        float s[KT];
        float mx = m;
#pragma unroll
        for (int k = 0; k < KT; k++) {
            const float4* kp = (const float4*)&sK[k][d0];
            float acc = 0.f;
#pragma unroll
            for (int i = 0; i < DHALF / 4; i++) {
                float4 v4 = kp[i];
                acc += q[4*i+0] * v4.x + q[4*i+1] * v4.y
                     + q[4*i+2] * v4.z + q[4*i+3] * v4.w;
            }
            acc += __shfl_xor_sync(0xffffffffu, acc, 1);
            s[k] = acc * SCALE;
            mx = fmaxf(mx, s[k]);
        }

        float corr = __expf(m - mx);
        m = mx;
        l *= corr;
#pragma unroll
        for (int d = 0; d < DHALF; d++) o[d] *= corr;

#pragma unroll
        for (int k = 0; k < KT; k++) {
            float p = __expf(s[k] - m);
            l += p;
            const float4* vp = (const float4*)&sV[k][d0];
#pragma unroll
            for (int i = 0; i < DHALF / 4; i++) {
                float4 v4 = vp[i];
                o[4*i+0] += p * v4.x; o[4*i+1] += p * v4.y;
                o[4*i+2] += p * v4.z; o[4*i+3] += p * v4.w;
            }
        }
    }

    float inv = 1.f / l;
    float* op = O + ((size_t)(b * SEQ + qrow)) * DIM + h * DH + d0;
#pragma unroll
    for (int i = 0; i < DHALF / 4; i++) {
        ((float4*)op)[i] = make_float4(o[4*i+0]*inv, o[4*i+1]*inv,
                                       o[4*i+2]*inv, o[4*i+3]*inv);
    }
}

// ---------------------------------------------------------------------------
extern "C" void kernel_launch(void* const* d_in, const int* in_sizes, int n_in,
                              void* d_out, int out_size) {
    const float* x  = (const float*)d_in[0];
    const float* WQ = (const float*)d_in[1];
    const float* WK = (const float*)d_in[2];
    const float* WV = (const float*)d_in[3];
    const float* WO = (const float*)d_in[4];
    float* out = (float*)d_out;

    float *pQ, *pK, *pV, *pC;
    cudaGetSymbolAddress((void**)&pQ, g_Q);
    cudaGetSymbolAddress((void**)&pK, g_K);
    cudaGetSymbolAddress((void**)&pV, g_V);
    cudaGetSymbolAddress((void**)&pC, g_C);

    dim3 ggrid(DIM / BN, MROWS / BM);     // (8, 64)
    gemm_tf32<<<ggrid, 256>>>(x, WQ, pQ, MROWS, DIM, DIM);
    gemm_tf32<<<ggrid, 256>>>(x, WK, pK, MROWS, DIM, DIM);
    gemm_tf32<<<ggrid, 256>>>(x, WV, pV, MROWS, DIM, DIM);

    dim3 agrid(SEQ / 128, HEADS, BATCH);  // (16, 16, 4)
    attn_kernel<<<agrid, 256>>>(pQ, pK, pV, pC);

    gemm_tf32<<<ggrid, 256>>>(pC, WO, out, MROWS, DIM, DIM);
}

// round 10
// speedup vs baseline: 3.7427x; 3.7427x over previous
#include <cuda_runtime.h>
#include <cuda_bf16.h>
#include <cstddef>
#include <cstdint>

// Problem constants
#define BATCH 4
#define SEQ   2048
#define DIM   1024
#define HEADS 16
#define DH    64
#define MROWS (BATCH*SEQ)  // 8192
#define SCALE 0.03125f     // 1/sqrt(1024)

// Scratch (allocation-free rule: __device__ globals)
__device__ float g_Q[(size_t)MROWS * DIM];
__device__ float g_K[(size_t)MROWS * DIM];
__device__ float g_V[(size_t)MROWS * DIM];
__device__ float g_C[(size_t)MROWS * DIM];

__device__ __forceinline__ float to_tf32(float x) {
    float r;
    asm("cvt.rna.tf32.f32 %0, %1;" : "=f"(r) : "f"(x));
    return r;
}

__device__ __forceinline__ void mma_tf32(float* c, const uint32_t* a, const uint32_t* b) {
    asm volatile(
        "mma.sync.aligned.m16n8k8.row.col.f32.tf32.tf32.f32 "
        "{%0,%1,%2,%3}, {%4,%5,%6,%7}, {%8,%9}, {%0,%1,%2,%3};"
        : "+f"(c[0]), "+f"(c[1]), "+f"(c[2]), "+f"(c[3])
        : "r"(a[0]), "r"(a[1]), "r"(a[2]), "r"(a[3]), "r"(b[0]), "r"(b[1]));
}

// ---------------------------------------------------------------------------
// TF32 mma.sync GEMM: C[M,N] = A[M,K] * B[K,N]  (unchanged, measured-good)
// ---------------------------------------------------------------------------
#define BM 128
#define BN 128
#define BK 16
#define SA_STR 20
#define SB_STR 136

__global__ __launch_bounds__(256) void gemm_tf32(const float* __restrict__ A,
                                                 const float* __restrict__ B,
                                                 float* __restrict__ C,
                                                 int M, int N, int K) {
    __shared__ float sA[BM * SA_STR];
    __shared__ float sB[BK * SB_STR];

    int tid  = threadIdx.x;
    int lane = tid & 31;
    int warp = tid >> 5;
    int gr = lane >> 2;
    int tq = lane & 3;
    int wm = (warp & 3) * 32;
    int wn = (warp >> 2) * 64;

    int bx = blockIdx.x, by = blockIdx.y;

    int a_row1 = tid >> 2;
    int a_kc   = (tid & 3) * 4;
    int b_kr   = tid >> 5;
    int b_nc   = (tid & 31) * 4;

    const float* Ap = A + (size_t)(by * BM + a_row1) * K + a_kc;
    const float* Bp = B + (size_t)b_kr * N + bx * BN + b_nc;

    float acc[2][8][4];
#pragma unroll
    for (int mt = 0; mt < 2; mt++)
#pragma unroll
        for (int nt = 0; nt < 8; nt++)
#pragma unroll
            for (int i = 0; i < 4; i++) acc[mt][nt][i] = 0.f;

    float4 ra0 = *(const float4*)(Ap);
    float4 ra1 = *(const float4*)(Ap + (size_t)64 * K);
    float4 rb0 = *(const float4*)(Bp);
    float4 rb1 = *(const float4*)(Bp + (size_t)8 * N);

    for (int k0 = 0; k0 < K; k0 += BK) {
        __syncthreads();
        {
            float4 t;
            t.x = to_tf32(ra0.x); t.y = to_tf32(ra0.y); t.z = to_tf32(ra0.z); t.w = to_tf32(ra0.w);
            *(float4*)&sA[a_row1 * SA_STR + a_kc] = t;
            t.x = to_tf32(ra1.x); t.y = to_tf32(ra1.y); t.z = to_tf32(ra1.z); t.w = to_tf32(ra1.w);
            *(float4*)&sA[(a_row1 + 64) * SA_STR + a_kc] = t;
            t.x = to_tf32(rb0.x); t.y = to_tf32(rb0.y); t.z = to_tf32(rb0.z); t.w = to_tf32(rb0.w);
            *(float4*)&sB[b_kr * SB_STR + b_nc] = t;
            t.x = to_tf32(rb1.x); t.y = to_tf32(rb1.y); t.z = to_tf32(rb1.z); t.w = to_tf32(rb1.w);
            *(float4*)&sB[(b_kr + 8) * SB_STR + b_nc] = t;
        }
        __syncthreads();

        if (k0 + BK < K) {
            Ap += BK;
            Bp += (size_t)BK * N;
            ra0 = *(const float4*)(Ap);
            ra1 = *(const float4*)(Ap + (size_t)64 * K);
            rb0 = *(const float4*)(Bp);
            rb1 = *(const float4*)(Bp + (size_t)8 * N);
        }

#pragma unroll
        for (int kt = 0; kt < BK; kt += 8) {
            uint32_t af[2][4];
            uint32_t bf[8][2];
#pragma unroll
            for (int mt = 0; mt < 2; mt++) {
                int base = (wm + mt * 16 + gr) * SA_STR + kt + tq;
                af[mt][0] = __float_as_uint(sA[base]);
                af[mt][1] = __float_as_uint(sA[base + 8 * SA_STR]);
                af[mt][2] = __float_as_uint(sA[base + 4]);
                af[mt][3] = __float_as_uint(sA[base + 8 * SA_STR + 4]);
            }
#pragma unroll
            for (int nt = 0; nt < 8; nt++) {
                int nb = wn + nt * 8 + gr;
                bf[nt][0] = __float_as_uint(sB[(kt + tq) * SB_STR + nb]);
                bf[nt][1] = __float_as_uint(sB[(kt + tq + 4) * SB_STR + nb]);
            }
#pragma unroll
            for (int mt = 0; mt < 2; mt++)
#pragma unroll
                for (int nt = 0; nt < 8; nt++)
                    mma_tf32(acc[mt][nt], af[mt], bf[nt]);
        }
    }

#pragma unroll
    for (int mt = 0; mt < 2; mt++) {
#pragma unroll
        for (int nt = 0; nt < 8; nt++) {
            int row = by * BM + wm + mt * 16 + gr;
            int col = bx * BN + wn + nt * 8 + 2 * tq;
            *(float2*)&C[(size_t)row * N + col] =
                make_float2(acc[mt][nt][0], acc[mt][nt][1]);
            *(float2*)&C[(size_t)(row + 8) * N + col] =
                make_float2(acc[mt][nt][2], acc[mt][nt][3]);
        }
    }
}

// ---------------------------------------------------------------------------
// FlashAttention-2 on tf32 mma.sync.
// CTA = one (b,h) x 64 queries; 4 warps x 16 query rows; key tiles of 32.
// grid = (SEQ/64, HEADS, BATCH), block = 128.
// ---------------------------------------------------------------------------
#define AQ 64
#define AK 32
#define KPAD 68   // sK row pitch: B-frag reads (row gr, col tq) conflict-free
#define VPAD 72   // sV row pitch: B-frag reads (row tq, col gr) conflict-free
#define PPAD 36   // sP row pitch: A-frag reads conflict-free

__global__ __launch_bounds__(128, 4) void attn_mma(const float* __restrict__ Q,
                                                   const float* __restrict__ K,
                                                   const float* __restrict__ V,
                                                   float* __restrict__ O) {
    __shared__ float sK[AK][KPAD];
    __shared__ float sV[AK][VPAD];
    __shared__ float sP[AQ][PPAD];

    const int b = blockIdx.z;
    const int h = blockIdx.y;
    const int qbase = blockIdx.x * AQ;
    const int tid  = threadIdx.x;
    const int warp = tid >> 5;
    const int lane = tid & 31;
    const int gr = lane >> 2;   // 0..7
    const int tq = lane & 3;    // 0..3

    const size_t hbase = (size_t)b * SEQ * DIM + (size_t)h * DH;

    // --- Q fragments in registers (scaled by SCALE, tf32-rounded) ---
    // A-frag m16n8k8: a0=(gr,tq) a1=(gr+8,tq) a2=(gr,tq+4) a3=(gr+8,tq+4)
    uint32_t qf[8][4];
    {
        const int r0 = qbase + warp * 16 + gr;
        const float* q0 = Q + hbase + (size_t)r0 * DIM;
        const float* q1 = Q + hbase + (size_t)(r0 + 8) * DIM;
#pragma unroll
        for (int ks = 0; ks < 8; ks++) {
            qf[ks][0] = __float_as_uint(to_tf32(SCALE * q0[ks * 8 + tq]));
            qf[ks][1] = __float_as_uint(to_tf32(SCALE * q1[ks * 8 + tq]));
            qf[ks][2] = __float_as_uint(to_tf32(SCALE * q0[ks * 8 + tq + 4]));
            qf[ks][3] = __float_as_uint(to_tf32(SCALE * q1[ks * 8 + tq + 4]));
        }
    }

    float oA[8][4];
#pragma unroll
    for (int nt = 0; nt < 8; nt++)
#pragma unroll
        for (int i = 0; i < 4; i++) oA[nt][i] = 0.f;

    float m0 = -1e30f, m1 = -1e30f, l0 = 0.f, l1 = 0.f;

    // staging map: K/V tiles are 32x64 f32 = 512 float4; thread does 4 each
    const int srow = tid >> 4;        // base row 0..7 (advance by 8)
    const int sc4  = tid & 15;        // float4 col 0..15

    for (int k0 = 0; k0 < SEQ; k0 += AK) {
        __syncthreads();
#pragma unroll
        for (int i = 0; i < 4; i++) {
            const int row = srow + i * 8;
            const float* kp = K + hbase + (size_t)(k0 + row) * DIM + sc4 * 4;
            const float* vp = V + hbase + (size_t)(k0 + row) * DIM + sc4 * 4;
            float4 kk = *(const float4*)kp;
            float4 vv = *(const float4*)vp;
            kk.x = to_tf32(kk.x); kk.y = to_tf32(kk.y); kk.z = to_tf32(kk.z); kk.w = to_tf32(kk.w);
            vv.x = to_tf32(vv.x); vv.y = to_tf32(vv.y); vv.z = to_tf32(vv.z); vv.w = to_tf32(vv.w);
            *(float4*)&sK[row][sc4 * 4] = kk;
            *(float4*)&sV[row][sc4 * 4] = vv;
        }
        __syncthreads();

        // --- QK^T: S[16 x 32] per warp (4 n-tiles of 8 keys) ---
        float sacc[4][4];
#pragma unroll
        for (int nt = 0; nt < 4; nt++)
#pragma unroll
            for (int i = 0; i < 4; i++) sacc[nt][i] = 0.f;

#pragma unroll
        for (int ks = 0; ks < 8; ks++) {
#pragma unroll
            for (int nt = 0; nt < 4; nt++) {
                uint32_t bf[2];
                bf[0] = __float_as_uint(sK[nt * 8 + gr][ks * 8 + tq]);
                bf[1] = __float_as_uint(sK[nt * 8 + gr][ks * 8 + tq + 4]);
                mma_tf32(sacc[nt], qf[ks], bf);
            }
        }

        // --- online softmax on fragments ---
        // D layout: c0=(gr,2tq) c1=(gr,2tq+1) c2=(gr+8,2tq) c3=(gr+8,2tq+1)
        float tm0 = fmaxf(fmaxf(sacc[0][0], sacc[0][1]), fmaxf(sacc[1][0], sacc[1][1]));
        tm0 = fmaxf(tm0, fmaxf(fmaxf(sacc[2][0], sacc[2][1]), fmaxf(sacc[3][0], sacc[3][1])));
        float tm1 = fmaxf(fmaxf(sacc[0][2], sacc[0][3]), fmaxf(sacc[1][2], sacc[1][3]));
        tm1 = fmaxf(tm1, fmaxf(fmaxf(sacc[2][2], sacc[2][3]), fmaxf(sacc[3][2], sacc[3][3])));
        tm0 = fmaxf(tm0, __shfl_xor_sync(0xffffffffu, tm0, 1));
        tm0 = fmaxf(tm0, __shfl_xor_sync(0xffffffffu, tm0, 2));
        tm1 = fmaxf(tm1, __shfl_xor_sync(0xffffffffu, tm1, 1));
        tm1 = fmaxf(tm1, __shfl_xor_sync(0xffffffffu, tm1, 2));

        const float nm0 = fmaxf(m0, tm0);
        const float nm1 = fmaxf(m1, tm1);
        const float corr0 = __expf(m0 - nm0);
        const float corr1 = __expf(m1 - nm1);
        m0 = nm0; m1 = nm1;

        float rs0 = 0.f, rs1 = 0.f;
        const int pr0 = warp * 16 + gr;
#pragma unroll
        for (int nt = 0; nt < 4; nt++) {
            float p0 = __expf(sacc[nt][0] - nm0);
            float p1 = __expf(sacc[nt][1] - nm0);
            float p2 = __expf(sacc[nt][2] - nm1);
            float p3 = __expf(sacc[nt][3] - nm1);
            rs0 += p0 + p1;
            rs1 += p2 + p3;
            *(float2*)&sP[pr0][nt * 8 + 2 * tq]     = make_float2(to_tf32(p0), to_tf32(p1));
            *(float2*)&sP[pr0 + 8][nt * 8 + 2 * tq] = make_float2(to_tf32(p2), to_tf32(p3));
        }
        rs0 += __shfl_xor_sync(0xffffffffu, rs0, 1);
        rs0 += __shfl_xor_sync(0xffffffffu, rs0, 2);
        rs1 += __shfl_xor_sync(0xffffffffu, rs1, 1);
        rs1 += __shfl_xor_sync(0xffffffffu, rs1, 2);
        l0 = l0 * corr0 + rs0;
        l1 = l1 * corr1 + rs1;

#pragma unroll
        for (int nt = 0; nt < 8; nt++) {
            oA[nt][0] *= corr0; oA[nt][1] *= corr0;
            oA[nt][2] *= corr1; oA[nt][3] *= corr1;
        }
        __syncwarp();

        // --- PV: O[16 x 64] += P[16 x 32] * V[32 x 64] ---
#pragma unroll
        for (int ks = 0; ks < 4; ks++) {
            uint32_t pf[4];
            pf[0] = __float_as_uint(sP[pr0][ks * 8 + tq]);
            pf[1] = __float_as_uint(sP[pr0 + 8][ks * 8 + tq]);
            pf[2] = __float_as_uint(sP[pr0][ks * 8 + tq + 4]);
            pf[3] = __float_as_uint(sP[pr0 + 8][ks * 8 + tq + 4]);
#pragma unroll
            for (int nt = 0; nt < 8; nt++) {
                uint32_t bf[2];
                bf[0] = __float_as_uint(sV[ks * 8 + tq][nt * 8 + gr]);
                bf[1] = __float_as_uint(sV[ks * 8 + tq + 4][nt * 8 + gr]);
                mma_tf32(oA[nt], pf, bf);
            }
        }
    }

    // --- epilogue ---
    const float inv0 = 1.f / l0;
    const float inv1 = 1.f / l1;
    const int r0 = qbase + warp * 16 + gr;
#pragma unroll
    for (int nt = 0; nt < 8; nt++) {
        const int col = nt * 8 + 2 * tq;
        *(float2*)&O[hbase + (size_t)r0 * DIM + col] =
            make_float2(oA[nt][0] * inv0, oA[nt][1] * inv0);
        *(float2*)&O[hbase + (size_t)(r0 + 8) * DIM + col] =
            make_float2(oA[nt][2] * inv1, oA[nt][3] * inv1);
    }
}

// ---------------------------------------------------------------------------
extern "C" void kernel_launch(void* const* d_in, const int* in_sizes, int n_in,
                              void* d_out, int out_size) {
    const float* x  = (const float*)d_in[0];
    const float* WQ = (const float*)d_in[1];
    const float* WK = (const float*)d_in[2];
    const float* WV = (const float*)d_in[3];
    const float* WO = (const float*)d_in[4];
    float* out = (float*)d_out;

    float *pQ, *pK, *pV, *pC;
    cudaGetSymbolAddress((void**)&pQ, g_Q);
    cudaGetSymbolAddress((void**)&pK, g_K);
    cudaGetSymbolAddress((void**)&pV, g_V);
    cudaGetSymbolAddress((void**)&pC, g_C);

    dim3 ggrid(DIM / BN, MROWS / BM);     // (8, 64)
    gemm_tf32<<<ggrid, 256>>>(x, WQ, pQ, MROWS, DIM, DIM);
    gemm_tf32<<<ggrid, 256>>>(x, WK, pK, MROWS, DIM, DIM);
    gemm_tf32<<<ggrid, 256>>>(x, WV, pV, MROWS, DIM, DIM);

    dim3 agrid(SEQ / AQ, HEADS, BATCH);   // (32, 16, 4)
    attn_mma<<<agrid, 128>>>(pQ, pK, pV, pC);

    gemm_tf32<<<ggrid, 256>>>(pC, WO, out, MROWS, DIM, DIM);
}

// round 13
// speedup vs baseline: 3.9815x; 1.0638x over previous
#include <cuda_runtime.h>
#include <cuda_bf16.h>
#include <cstddef>
#include <cstdint>

// Problem constants
#define BATCH 4
#define SEQ   2048
#define DIM   1024
#define HEADS 16
#define DH    64
#define MROWS (BATCH*SEQ)  // 8192
#define SCALE 0.03125f     // 1/sqrt(1024)

// Scratch (allocation-free rule: __device__ globals)
__device__ float g_Q[(size_t)MROWS * DIM];
__device__ float g_K[(size_t)MROWS * DIM];
__device__ float g_V[(size_t)MROWS * DIM];
__device__ float g_C[(size_t)MROWS * DIM];

__device__ __forceinline__ float to_tf32(float x) {
    float r;
    asm("cvt.rna.tf32.f32 %0, %1;" : "=f"(r) : "f"(x));
    return r;
}

__device__ __forceinline__ void mma_tf32(float* c, const uint32_t* a, const uint32_t* b) {
    asm volatile(
        "mma.sync.aligned.m16n8k8.row.col.f32.tf32.tf32.f32 "
        "{%0,%1,%2,%3}, {%4,%5,%6,%7}, {%8,%9}, {%0,%1,%2,%3};"
        : "+f"(c[0]), "+f"(c[1]), "+f"(c[2]), "+f"(c[3])
        : "r"(a[0]), "r"(a[1]), "r"(a[2]), "r"(a[3]), "r"(b[0]), "r"(b[1]));
}

__device__ __forceinline__ uint32_t smem_u32(const void* p) {
    uint32_t a;
    asm("{ .reg .u64 t; cvta.to.shared.u64 t, %1; cvt.u32.u64 %0, t; }"
        : "=r"(a) : "l"(p));
    return a;
}

__device__ __forceinline__ void cp_async16(void* smem, const void* gmem) {
    asm volatile("cp.async.cg.shared.global [%0], [%1], 16;"
                 :: "r"(smem_u32(smem)), "l"(gmem) : "memory");
}
#define CP_COMMIT() asm volatile("cp.async.commit_group;" ::: "memory")
#define CP_WAIT0()  asm volatile("cp.async.wait_group 0;" ::: "memory")

// ---------------------------------------------------------------------------
// TF32 mma.sync GEMM: C[M,N] = A[M,K] * B[K,N]  (unchanged, measured-good)
// ---------------------------------------------------------------------------
#define BM 128
#define BN 128
#define BK 16
#define SA_STR 20
#define SB_STR 136

__global__ __launch_bounds__(256) void gemm_tf32(const float* __restrict__ A,
                                                 const float* __restrict__ B,
                                                 float* __restrict__ C,
                                                 int M, int N, int K) {
    __shared__ float sA[BM * SA_STR];
    __shared__ float sB[BK * SB_STR];

    int tid  = threadIdx.x;
    int lane = tid & 31;
    int warp = tid >> 5;
    int gr = lane >> 2;
    int tq = lane & 3;
    int wm = (warp & 3) * 32;
    int wn = (warp >> 2) * 64;

    int bx = blockIdx.x, by = blockIdx.y;

    int a_row1 = tid >> 2;
    int a_kc   = (tid & 3) * 4;
    int b_kr   = tid >> 5;
    int b_nc   = (tid & 31) * 4;

    const float* Ap = A + (size_t)(by * BM + a_row1) * K + a_kc;
    const float* Bp = B + (size_t)b_kr * N + bx * BN + b_nc;

    float acc[2][8][4];
#pragma unroll
    for (int mt = 0; mt < 2; mt++)
#pragma unroll
        for (int nt = 0; nt < 8; nt++)
#pragma unroll
            for (int i = 0; i < 4; i++) acc[mt][nt][i] = 0.f;

    float4 ra0 = *(const float4*)(Ap);
    float4 ra1 = *(const float4*)(Ap + (size_t)64 * K);
    float4 rb0 = *(const float4*)(Bp);
    float4 rb1 = *(const float4*)(Bp + (size_t)8 * N);

    for (int k0 = 0; k0 < K; k0 += BK) {
        __syncthreads();
        {
            float4 t;
            t.x = to_tf32(ra0.x); t.y = to_tf32(ra0.y); t.z = to_tf32(ra0.z); t.w = to_tf32(ra0.w);
            *(float4*)&sA[a_row1 * SA_STR + a_kc] = t;
            t.x = to_tf32(ra1.x); t.y = to_tf32(ra1.y); t.z = to_tf32(ra1.z); t.w = to_tf32(ra1.w);
            *(float4*)&sA[(a_row1 + 64) * SA_STR + a_kc] = t;
            t.x = to_tf32(rb0.x); t.y = to_tf32(rb0.y); t.z = to_tf32(rb0.z); t.w = to_tf32(rb0.w);
            *(float4*)&sB[b_kr * SB_STR + b_nc] = t;
            t.x = to_tf32(rb1.x); t.y = to_tf32(rb1.y); t.z = to_tf32(rb1.z); t.w = to_tf32(rb1.w);
            *(float4*)&sB[(b_kr + 8) * SB_STR + b_nc] = t;
        }
        __syncthreads();

        if (k0 + BK < K) {
            Ap += BK;
            Bp += (size_t)BK * N;
            ra0 = *(const float4*)(Ap);
            ra1 = *(const float4*)(Ap + (size_t)64 * K);
            rb0 = *(const float4*)(Bp);
            rb1 = *(const float4*)(Bp + (size_t)8 * N);
        }

#pragma unroll
        for (int kt = 0; kt < BK; kt += 8) {
            uint32_t af[2][4];
            uint32_t bf[8][2];
#pragma unroll
            for (int mt = 0; mt < 2; mt++) {
                int base = (wm + mt * 16 + gr) * SA_STR + kt + tq;
                af[mt][0] = __float_as_uint(sA[base]);
                af[mt][1] = __float_as_uint(sA[base + 8 * SA_STR]);
                af[mt][2] = __float_as_uint(sA[base + 4]);
                af[mt][3] = __float_as_uint(sA[base + 8 * SA_STR + 4]);
            }
#pragma unroll
            for (int nt = 0; nt < 8; nt++) {
                int nb = wn + nt * 8 + gr;
                bf[nt][0] = __float_as_uint(sB[(kt + tq) * SB_STR + nb]);
                bf[nt][1] = __float_as_uint(sB[(kt + tq + 4) * SB_STR + nb]);
            }
#pragma unroll
            for (int mt = 0; mt < 2; mt++)
#pragma unroll
                for (int nt = 0; nt < 8; nt++)
                    mma_tf32(acc[mt][nt], af[mt], bf[nt]);
        }
    }

#pragma unroll
    for (int mt = 0; mt < 2; mt++) {
#pragma unroll
        for (int nt = 0; nt < 8; nt++) {
            int row = by * BM + wm + mt * 16 + gr;
            int col = bx * BN + wn + nt * 8 + 2 * tq;
            *(float2*)&C[(size_t)row * N + col] =
                make_float2(acc[mt][nt][0], acc[mt][nt][1]);
            *(float2*)&C[(size_t)(row + 8) * N + col] =
                make_float2(acc[mt][nt][2], acc[mt][nt][3]);
        }
    }
}

// ---------------------------------------------------------------------------
// FlashAttention-2 on tf32 mma.sync with 2-stage cp.async K/V pipeline.
// CTA = one (b,h) x 64 queries; 4 warps x 16 query rows; key tiles of 32.
// grid = (SEQ/64, HEADS, BATCH), block = 128.
// ---------------------------------------------------------------------------
#define AQ 64
#define AK 32
#define KPAD 68   // 272B pitch (16B-aligned); B-frag reads conflict-free
#define VPAD 72   // 288B pitch (16B-aligned); B-frag reads conflict-free
#define PPAD 36

__global__ __launch_bounds__(128, 4) void attn_mma(const float* __restrict__ Q,
                                                   const float* __restrict__ K,
                                                   const float* __restrict__ V,
                                                   float* __restrict__ O) {
    __shared__ float sK[2][AK][KPAD];
    __shared__ float sV[2][AK][VPAD];
    __shared__ float sP[AQ][PPAD];

    const int b = blockIdx.z;
    const int h = blockIdx.y;
    const int qbase = blockIdx.x * AQ;
    const int tid  = threadIdx.x;
    const int warp = tid >> 5;
    const int lane = tid & 31;
    const int gr = lane >> 2;   // 0..7
    const int tq = lane & 3;    // 0..3

    const size_t hbase = (size_t)b * SEQ * DIM + (size_t)h * DH;

    // staging map: K/V tiles are 32x64 f32 = 512 float4; thread does 4 each
    const int srow = tid >> 4;        // base row 0..7 (advance by 8)
    const int sc4  = tid & 15;        // float4 col 0..15

    // --- Q fragments in registers (scaled, tf32-rounded) ---
    uint32_t qf[8][4];
    {
        const int r0 = qbase + warp * 16 + gr;
        const float* q0 = Q + hbase + (size_t)r0 * DIM;
        const float* q1 = Q + hbase + (size_t)(r0 + 8) * DIM;
#pragma unroll
        for (int ks = 0; ks < 8; ks++) {
            qf[ks][0] = __float_as_uint(to_tf32(SCALE * q0[ks * 8 + tq]));
            qf[ks][1] = __float_as_uint(to_tf32(SCALE * q1[ks * 8 + tq]));
            qf[ks][2] = __float_as_uint(to_tf32(SCALE * q0[ks * 8 + tq + 4]));
            qf[ks][3] = __float_as_uint(to_tf32(SCALE * q1[ks * 8 + tq + 4]));
        }
    }

    float oA[8][4];
#pragma unroll
    for (int nt = 0; nt < 8; nt++)
#pragma unroll
        for (int i = 0; i < 4; i++) oA[nt][i] = 0.f;

    float m0 = -1e30f, m1 = -1e30f, l0 = 0.f, l1 = 0.f;

    // Prologue: issue tile 0 into buffer 0
#pragma unroll
    for (int i = 0; i < 4; i++) {
        const int row = srow + i * 8;
        cp_async16(&sK[0][row][sc4 * 4], K + hbase + (size_t)row * DIM + sc4 * 4);
        cp_async16(&sV[0][row][sc4 * 4], V + hbase + (size_t)row * DIM + sc4 * 4);
    }
    CP_COMMIT();

    const int NIT = SEQ / AK;   // 64
    for (int it = 0; it < NIT; it++) {
        CP_WAIT0();
        __syncthreads();        // tile `it` ready; all compute on buf[it^1] done

        if (it + 1 < NIT) {
            const int nbuf = (it + 1) & 1;
            const size_t tb = hbase + (size_t)(it + 1) * AK * DIM;
#pragma unroll
            for (int i = 0; i < 4; i++) {
                const int row = srow + i * 8;
                cp_async16(&sK[nbuf][row][sc4 * 4], K + tb + (size_t)row * DIM + sc4 * 4);
                cp_async16(&sV[nbuf][row][sc4 * 4], V + tb + (size_t)row * DIM + sc4 * 4);
            }
            CP_COMMIT();
        }

        const int cb = it & 1;

        // --- QK^T: S[16 x 32] per warp ---
        float sacc[4][4];
#pragma unroll
        for (int nt = 0; nt < 4; nt++)
#pragma unroll
            for (int i = 0; i < 4; i++) sacc[nt][i] = 0.f;

#pragma unroll
        for (int ks = 0; ks < 8; ks++) {
#pragma unroll
            for (int nt = 0; nt < 4; nt++) {
                uint32_t bf[2];
                bf[0] = __float_as_uint(sK[cb][nt * 8 + gr][ks * 8 + tq]);
                bf[1] = __float_as_uint(sK[cb][nt * 8 + gr][ks * 8 + tq + 4]);
                mma_tf32(sacc[nt], qf[ks], bf);
            }
        }

        // --- online softmax on fragments ---
        float tm0 = fmaxf(fmaxf(sacc[0][0], sacc[0][1]), fmaxf(sacc[1][0], sacc[1][1]));
        tm0 = fmaxf(tm0, fmaxf(fmaxf(sacc[2][0], sacc[2][1]), fmaxf(sacc[3][0], sacc[3][1])));
        float tm1 = fmaxf(fmaxf(sacc[0][2], sacc[0][3]), fmaxf(sacc[1][2], sacc[1][3]));
        tm1 = fmaxf(tm1, fmaxf(fmaxf(sacc[2][2], sacc[2][3]), fmaxf(sacc[3][2], sacc[3][3])));
        tm0 = fmaxf(tm0, __shfl_xor_sync(0xffffffffu, tm0, 1));
        tm0 = fmaxf(tm0, __shfl_xor_sync(0xffffffffu, tm0, 2));
        tm1 = fmaxf(tm1, __shfl_xor_sync(0xffffffffu, tm1, 1));
        tm1 = fmaxf(tm1, __shfl_xor_sync(0xffffffffu, tm1, 2));

        const float nm0 = fmaxf(m0, tm0);
        const float nm1 = fmaxf(m1, tm1);
        const float corr0 = __expf(m0 - nm0);
        const float corr1 = __expf(m1 - nm1);
        m0 = nm0; m1 = nm1;

        float rs0 = 0.f, rs1 = 0.f;
        const int pr0 = warp * 16 + gr;
#pragma unroll
        for (int nt = 0; nt < 4; nt++) {
            float p0 = __expf(sacc[nt][0] - nm0);
            float p1 = __expf(sacc[nt][1] - nm0);
            float p2 = __expf(sacc[nt][2] - nm1);
            float p3 = __expf(sacc[nt][3] - nm1);
            rs0 += p0 + p1;
            rs1 += p2 + p3;
            *(float2*)&sP[pr0][nt * 8 + 2 * tq]     = make_float2(to_tf32(p0), to_tf32(p1));
            *(float2*)&sP[pr0 + 8][nt * 8 + 2 * tq] = make_float2(to_tf32(p2), to_tf32(p3));
        }
        rs0 += __shfl_xor_sync(0xffffffffu, rs0, 1);
        rs0 += __shfl_xor_sync(0xffffffffu, rs0, 2);
        rs1 += __shfl_xor_sync(0xffffffffu, rs1, 1);
        rs1 += __shfl_xor_sync(0xffffffffu, rs1, 2);
        l0 = l0 * corr0 + rs0;
        l1 = l1 * corr1 + rs1;

#pragma unroll
        for (int nt = 0; nt < 8; nt++) {
            oA[nt][0] *= corr0; oA[nt][1] *= corr0;
            oA[nt][2] *= corr1; oA[nt][3] *= corr1;
        }
        __syncwarp();

        // --- PV: O[16 x 64] += P[16 x 32] * V[32 x 64] ---
#pragma unroll
        for (int ks = 0; ks < 4; ks++) {
            uint32_t pf[4];
            pf[0] = __float_as_uint(sP[pr0][ks * 8 + tq]);
            pf[1] = __float_as_uint(sP[pr0 + 8][ks * 8 + tq]);
            pf[2] = __float_as_uint(sP[pr0][ks * 8 + tq + 4]);
            pf[3] = __float_as_uint(sP[pr0 + 8][ks * 8 + tq + 4]);
#pragma unroll
            for (int nt = 0; nt < 8; nt++) {
                uint32_t bf[2];
                bf[0] = __float_as_uint(sV[cb][ks * 8 + tq][nt * 8 + gr]);
                bf[1] = __float_as_uint(sV[cb][ks * 8 + tq + 4][nt * 8 + gr]);
                mma_tf32(oA[nt], pf, bf);
            }
        }
    }

    // --- epilogue ---
    const float inv0 = 1.f / l0;
    const float inv1 = 1.f / l1;
    const int r0 = qbase + warp * 16 + gr;
#pragma unroll
    for (int nt = 0; nt < 8; nt++) {
        const int col = nt * 8 + 2 * tq;
        *(float2*)&O[hbase + (size_t)r0 * DIM + col] =
            make_float2(oA[nt][0] * inv0, oA[nt][1] * inv0);
        *(float2*)&O[hbase + (size_t)(r0 + 8) * DIM + col] =
            make_float2(oA[nt][2] * inv1, oA[nt][3] * inv1);
    }
}

// ---------------------------------------------------------------------------
extern "C" void kernel_launch(void* const* d_in, const int* in_sizes, int n_in,
                              void* d_out, int out_size) {
    const float* x  = (const float*)d_in[0];
    const float* WQ = (const float*)d_in[1];
    const float* WK = (const float*)d_in[2];
    const float* WV = (const float*)d_in[3];
    const float* WO = (const float*)d_in[4];
    float* out = (float*)d_out;

    float *pQ, *pK, *pV, *pC;
    cudaGetSymbolAddress((void**)&pQ, g_Q);
    cudaGetSymbolAddress((void**)&pK, g_K);
    cudaGetSymbolAddress((void**)&pV, g_V);
    cudaGetSymbolAddress((void**)&pC, g_C);

    dim3 ggrid(DIM / BN, MROWS / BM);     // (8, 64)
    gemm_tf32<<<ggrid, 256>>>(x, WQ, pQ, MROWS, DIM, DIM);
    gemm_tf32<<<ggrid, 256>>>(x, WK, pK, MROWS, DIM, DIM);
    gemm_tf32<<<ggrid, 256>>>(x, WV, pV, MROWS, DIM, DIM);

    dim3 agrid(SEQ / AQ, HEADS, BATCH);   // (32, 16, 4)
    attn_mma<<<agrid, 128>>>(pQ, pK, pV, pC);

    gemm_tf32<<<ggrid, 256>>>(pC, WO, out, MROWS, DIM, DIM);
}

// round 14
// speedup vs baseline: 4.0660x; 1.0212x over previous
#include <cuda_runtime.h>
#include <cuda_bf16.h>
#include <cstddef>
#include <cstdint>

// Problem constants
#define BATCH 4
#define SEQ   2048
#define DIM   1024
#define HEADS 16
#define DH    64
#define MROWS (BATCH*SEQ)  // 8192
#define SCALE 0.03125f     // 1/sqrt(1024)

// Scratch (allocation-free rule: __device__ globals)
__device__ float g_Q[(size_t)MROWS * DIM];
__device__ float g_K[(size_t)MROWS * DIM];
__device__ float g_V[(size_t)MROWS * DIM];
__device__ float g_C[(size_t)MROWS * DIM];

__device__ __forceinline__ float to_tf32(float x) {
    float r;
    asm("cvt.rna.tf32.f32 %0, %1;" : "=f"(r) : "f"(x));
    return r;
}

__device__ __forceinline__ void mma_tf32(float* c, const uint32_t* a, const uint32_t* b) {
    asm volatile(
        "mma.sync.aligned.m16n8k8.row.col.f32.tf32.tf32.f32 "
        "{%0,%1,%2,%3}, {%4,%5,%6,%7}, {%8,%9}, {%0,%1,%2,%3};"
        : "+f"(c[0]), "+f"(c[1]), "+f"(c[2]), "+f"(c[3])
        : "r"(a[0]), "r"(a[1]), "r"(a[2]), "r"(a[3]), "r"(b[0]), "r"(b[1]));
}

__device__ __forceinline__ uint32_t smem_u32(const void* p) {
    uint32_t a;
    asm("{ .reg .u64 t; cvta.to.shared.u64 t, %1; cvt.u32.u64 %0, t; }"
        : "=r"(a) : "l"(p));
    return a;
}

__device__ __forceinline__ void cp_async16(void* smem, const void* gmem) {
    asm volatile("cp.async.cg.shared.global [%0], [%1], 16;"
                 :: "r"(smem_u32(smem)), "l"(gmem) : "memory");
}
#define CP_COMMIT() asm volatile("cp.async.commit_group;" ::: "memory")
#define CP_WAIT0()  asm volatile("cp.async.wait_group 0;" ::: "memory")

// ---------------------------------------------------------------------------
// TF32 mma.sync GEMM, 2-stage smem double buffer (cvt.rna preserved).
// C[M,N] = A[M,K] * B[K,N]; 128x128x16 tile, 256 threads, warp tile 32x64.
// One __syncthreads per k-iter; global loads + STS hidden behind mma loop.
// ---------------------------------------------------------------------------
#define BM 128
#define BN 128
#define BK 16
#define SA_STR 20
#define SB_STR 136

__global__ __launch_bounds__(256) void gemm_tf32(const float* __restrict__ A,
                                                 const float* __restrict__ B,
                                                 float* __restrict__ C,
                                                 int M, int N, int K) {
    __shared__ float sA[2][BM * SA_STR];
    __shared__ float sB[2][BK * SB_STR];

    int tid  = threadIdx.x;
    int lane = tid & 31;
    int warp = tid >> 5;
    int gr = lane >> 2;
    int tq = lane & 3;
    int wm = (warp & 3) * 32;
    int wn = (warp >> 2) * 64;

    int bx = blockIdx.x, by = blockIdx.y;

    int a_row1 = tid >> 2;
    int a_kc   = (tid & 3) * 4;
    int b_kr   = tid >> 5;
    int b_nc   = (tid & 31) * 4;

    const float* Ap = A + (size_t)(by * BM + a_row1) * K + a_kc;
    const float* Bp = B + (size_t)b_kr * N + bx * BN + b_nc;

    float acc[2][8][4];
#pragma unroll
    for (int mt = 0; mt < 2; mt++)
#pragma unroll
        for (int nt = 0; nt < 8; nt++)
#pragma unroll
            for (int i = 0; i < 4; i++) acc[mt][nt][i] = 0.f;

    // Load tile 0 and stage into buffer 0
    float4 ra0 = *(const float4*)(Ap);
    float4 ra1 = *(const float4*)(Ap + (size_t)64 * K);
    float4 rb0 = *(const float4*)(Bp);
    float4 rb1 = *(const float4*)(Bp + (size_t)8 * N);
    {
        float4 t;
        t.x = to_tf32(ra0.x); t.y = to_tf32(ra0.y); t.z = to_tf32(ra0.z); t.w = to_tf32(ra0.w);
        *(float4*)&sA[0][a_row1 * SA_STR + a_kc] = t;
        t.x = to_tf32(ra1.x); t.y = to_tf32(ra1.y); t.z = to_tf32(ra1.z); t.w = to_tf32(ra1.w);
        *(float4*)&sA[0][(a_row1 + 64) * SA_STR + a_kc] = t;
        t.x = to_tf32(rb0.x); t.y = to_tf32(rb0.y); t.z = to_tf32(rb0.z); t.w = to_tf32(rb0.w);
        *(float4*)&sB[0][b_kr * SB_STR + b_nc] = t;
        t.x = to_tf32(rb1.x); t.y = to_tf32(rb1.y); t.z = to_tf32(rb1.z); t.w = to_tf32(rb1.w);
        *(float4*)&sB[0][(b_kr + 8) * SB_STR + b_nc] = t;
    }
    __syncthreads();

    const int NIT = K / BK;   // 64
    for (int it = 0; it < NIT; it++) {
        const int cb = it & 1;

        // Issue next tile's global loads early (latency hidden by mma loop)
        if (it + 1 < NIT) {
            Ap += BK;
            Bp += (size_t)BK * N;
            ra0 = *(const float4*)(Ap);
            ra1 = *(const float4*)(Ap + (size_t)64 * K);
            rb0 = *(const float4*)(Bp);
            rb1 = *(const float4*)(Bp + (size_t)8 * N);
        }

#pragma unroll
        for (int kt = 0; kt < BK; kt += 8) {
            uint32_t af[2][4];
            uint32_t bf[8][2];
#pragma unroll
            for (int mt = 0; mt < 2; mt++) {
                int base = (wm + mt * 16 + gr) * SA_STR + kt + tq;
                af[mt][0] = __float_as_uint(sA[cb][base]);
                af[mt][1] = __float_as_uint(sA[cb][base + 8 * SA_STR]);
                af[mt][2] = __float_as_uint(sA[cb][base + 4]);
                af[mt][3] = __float_as_uint(sA[cb][base + 8 * SA_STR + 4]);
            }
#pragma unroll
            for (int nt = 0; nt < 8; nt++) {
                int nb = wn + nt * 8 + gr;
                bf[nt][0] = __float_as_uint(sB[cb][(kt + tq) * SB_STR + nb]);
                bf[nt][1] = __float_as_uint(sB[cb][(kt + tq + 4) * SB_STR + nb]);
            }
#pragma unroll
            for (int mt = 0; mt < 2; mt++)
#pragma unroll
                for (int nt = 0; nt < 8; nt++)
                    mma_tf32(acc[mt][nt], af[mt], bf[nt]);
        }

        // Stage next tile into the alternate buffer (safe: that buffer's
        // consumers finished before the barrier at end of iter it-1)
        if (it + 1 < NIT) {
            const int nb = (it + 1) & 1;
            float4 t;
            t.x = to_tf32(ra0.x); t.y = to_tf32(ra0.y); t.z = to_tf32(ra0.z); t.w = to_tf32(ra0.w);
            *(float4*)&sA[nb][a_row1 * SA_STR + a_kc] = t;
            t.x = to_tf32(ra1.x); t.y = to_tf32(ra1.y); t.z = to_tf32(ra1.z); t.w = to_tf32(ra1.w);
            *(float4*)&sA[nb][(a_row1 + 64) * SA_STR + a_kc] = t;
            t.x = to_tf32(rb0.x); t.y = to_tf32(rb0.y); t.z = to_tf32(rb0.z); t.w = to_tf32(rb0.w);
            *(float4*)&sB[nb][b_kr * SB_STR + b_nc] = t;
            t.x = to_tf32(rb1.x); t.y = to_tf32(rb1.y); t.z = to_tf32(rb1.z); t.w = to_tf32(rb1.w);
            *(float4*)&sB[nb][(b_kr + 8) * SB_STR + b_nc] = t;
            __syncthreads();
        }
    }

#pragma unroll
    for (int mt = 0; mt < 2; mt++) {
#pragma unroll
        for (int nt = 0; nt < 8; nt++) {
            int row = by * BM + wm + mt * 16 + gr;
            int col = bx * BN + wn + nt * 8 + 2 * tq;
            *(float2*)&C[(size_t)row * N + col] =
                make_float2(acc[mt][nt][0], acc[mt][nt][1]);
            *(float2*)&C[(size_t)(row + 8) * N + col] =
                make_float2(acc[mt][nt][2], acc[mt][nt][3]);
        }
    }
}

// ---------------------------------------------------------------------------
// FlashAttention-2 on tf32 mma.sync with 2-stage cp.async K/V pipeline.
// (unchanged, measured-good: 493us)
// ---------------------------------------------------------------------------
#define AQ 64
#define AK 32
#define KPAD 68
#define VPAD 72
#define PPAD 36

__global__ __launch_bounds__(128, 4) void attn_mma(const float* __restrict__ Q,
                                                   const float* __restrict__ K,
                                                   const float* __restrict__ V,
                                                   float* __restrict__ O) {
    __shared__ float sK[2][AK][KPAD];
    __shared__ float sV[2][AK][VPAD];
    __shared__ float sP[AQ][PPAD];

    const int b = blockIdx.z;
    const int h = blockIdx.y;
    const int qbase = blockIdx.x * AQ;
    const int tid  = threadIdx.x;
    const int warp = tid >> 5;
    const int lane = tid & 31;
    const int gr = lane >> 2;
    const int tq = lane & 3;

    const size_t hbase = (size_t)b * SEQ * DIM + (size_t)h * DH;

    const int srow = tid >> 4;
    const int sc4  = tid & 15;

    uint32_t qf[8][4];
    {
        const int r0 = qbase + warp * 16 + gr;
        const float* q0 = Q + hbase + (size_t)r0 * DIM;
        const float* q1 = Q + hbase + (size_t)(r0 + 8) * DIM;
#pragma unroll
        for (int ks = 0; ks < 8; ks++) {
            qf[ks][0] = __float_as_uint(to_tf32(SCALE * q0[ks * 8 + tq]));
            qf[ks][1] = __float_as_uint(to_tf32(SCALE * q1[ks * 8 + tq]));
            qf[ks][2] = __float_as_uint(to_tf32(SCALE * q0[ks * 8 + tq + 4]));
            qf[ks][3] = __float_as_uint(to_tf32(SCALE * q1[ks * 8 + tq + 4]));
        }
    }

    float oA[8][4];
#pragma unroll
    for (int nt = 0; nt < 8; nt++)
#pragma unroll
        for (int i = 0; i < 4; i++) oA[nt][i] = 0.f;

    float m0 = -1e30f, m1 = -1e30f, l0 = 0.f, l1 = 0.f;

#pragma unroll
    for (int i = 0; i < 4; i++) {
        const int row = srow + i * 8;
        cp_async16(&sK[0][row][sc4 * 4], K + hbase + (size_t)row * DIM + sc4 * 4);
        cp_async16(&sV[0][row][sc4 * 4], V + hbase + (size_t)row * DIM + sc4 * 4);
    }
    CP_COMMIT();

    const int NIT = SEQ / AK;   // 64
    for (int it = 0; it < NIT; it++) {
        CP_WAIT0();
        __syncthreads();

        if (it + 1 < NIT) {
            const int nbuf = (it + 1) & 1;
            const size_t tb = hbase + (size_t)(it + 1) * AK * DIM;
#pragma unroll
            for (int i = 0; i < 4; i++) {
                const int row = srow + i * 8;
                cp_async16(&sK[nbuf][row][sc4 * 4], K + tb + (size_t)row * DIM + sc4 * 4);
                cp_async16(&sV[nbuf][row][sc4 * 4], V + tb + (size_t)row * DIM + sc4 * 4);
            }
            CP_COMMIT();
        }

        const int cb = it & 1;

        float sacc[4][4];
#pragma unroll
        for (int nt = 0; nt < 4; nt++)
#pragma unroll
            for (int i = 0; i < 4; i++) sacc[nt][i] = 0.f;

#pragma unroll
        for (int ks = 0; ks < 8; ks++) {
#pragma unroll
            for (int nt = 0; nt < 4; nt++) {
                uint32_t bf[2];
                bf[0] = __float_as_uint(sK[cb][nt * 8 + gr][ks * 8 + tq]);
                bf[1] = __float_as_uint(sK[cb][nt * 8 + gr][ks * 8 + tq + 4]);
                mma_tf32(sacc[nt], qf[ks], bf);
            }
        }

        float tm0 = fmaxf(fmaxf(sacc[0][0], sacc[0][1]), fmaxf(sacc[1][0], sacc[1][1]));
        tm0 = fmaxf(tm0, fmaxf(fmaxf(sacc[2][0], sacc[2][1]), fmaxf(sacc[3][0], sacc[3][1])));
        float tm1 = fmaxf(fmaxf(sacc[0][2], sacc[0][3]), fmaxf(sacc[1][2], sacc[1][3]));
        tm1 = fmaxf(tm1, fmaxf(fmaxf(sacc[2][2], sacc[2][3]), fmaxf(sacc[3][2], sacc[3][3])));
        tm0 = fmaxf(tm0, __shfl_xor_sync(0xffffffffu, tm0, 1));
        tm0 = fmaxf(tm0, __shfl_xor_sync(0xffffffffu, tm0, 2));
        tm1 = fmaxf(tm1, __shfl_xor_sync(0xffffffffu, tm1, 1));
        tm1 = fmaxf(tm1, __shfl_xor_sync(0xffffffffu, tm1, 2));

        const float nm0 = fmaxf(m0, tm0);
        const float nm1 = fmaxf(m1, tm1);
        const float corr0 = __expf(m0 - nm0);
        const float corr1 = __expf(m1 - nm1);
        m0 = nm0; m1 = nm1;

        float rs0 = 0.f, rs1 = 0.f;
        const int pr0 = warp * 16 + gr;
#pragma unroll
        for (int nt = 0; nt < 4; nt++) {
            float p0 = __expf(sacc[nt][0] - nm0);
            float p1 = __expf(sacc[nt][1] - nm0);
            float p2 = __expf(sacc[nt][2] - nm1);
            float p3 = __expf(sacc[nt][3] - nm1);
            rs0 += p0 + p1;
            rs1 += p2 + p3;
            *(float2*)&sP[pr0][nt * 8 + 2 * tq]     = make_float2(to_tf32(p0), to_tf32(p1));
            *(float2*)&sP[pr0 + 8][nt * 8 + 2 * tq] = make_float2(to_tf32(p2), to_tf32(p3));
        }
        rs0 += __shfl_xor_sync(0xffffffffu, rs0, 1);
        rs0 += __shfl_xor_sync(0xffffffffu, rs0, 2);
        rs1 += __shfl_xor_sync(0xffffffffu, rs1, 1);
        rs1 += __shfl_xor_sync(0xffffffffu, rs1, 2);
        l0 = l0 * corr0 + rs0;
        l1 = l1 * corr1 + rs1;

#pragma unroll
        for (int nt = 0; nt < 8; nt++) {
            oA[nt][0] *= corr0; oA[nt][1] *= corr0;
            oA[nt][2] *= corr1; oA[nt][3] *= corr1;
        }
        __syncwarp();

#pragma unroll
        for (int ks = 0; ks < 4; ks++) {
            uint32_t pf[4];
            pf[0] = __float_as_uint(sP[pr0][ks * 8 + tq]);
            pf[1] = __float_as_uint(sP[pr0 + 8][ks * 8 + tq]);
            pf[2] = __float_as_uint(sP[pr0][ks * 8 + tq + 4]);
            pf[3] = __float_as_uint(sP[pr0 + 8][ks * 8 + tq + 4]);
#pragma unroll
            for (int nt = 0; nt < 8; nt++) {
                uint32_t bf[2];
                bf[0] = __float_as_uint(sV[cb][ks * 8 + tq][nt * 8 + gr]);
                bf[1] = __float_as_uint(sV[cb][ks * 8 + tq + 4][nt * 8 + gr]);
                mma_tf32(oA[nt], pf, bf);
            }
        }
    }

    const float inv0 = 1.f / l0;
    const float inv1 = 1.f / l1;
    const int r0 = qbase + warp * 16 + gr;
#pragma unroll
    for (int nt = 0; nt < 8; nt++) {
        const int col = nt * 8 + 2 * tq;
        *(float2*)&O[hbase + (size_t)r0 * DIM + col] =
            make_float2(oA[nt][0] * inv0, oA[nt][1] * inv0);
        *(float2*)&O[hbase + (size_t)(r0 + 8) * DIM + col] =
            make_float2(oA[nt][2] * inv1, oA[nt][3] * inv1);
    }
}

// ---------------------------------------------------------------------------
extern "C" void kernel_launch(void* const* d_in, const int* in_sizes, int n_in,
                              void* d_out, int out_size) {
    const float* x  = (const float*)d_in[0];
    const float* WQ = (const float*)d_in[1];
    const float* WK = (const float*)d_in[2];
    const float* WV = (const float*)d_in[3];
    const float* WO = (const float*)d_in[4];
    float* out = (float*)d_out;

    float *pQ, *pK, *pV, *pC;
    cudaGetSymbolAddress((void**)&pQ, g_Q);
    cudaGetSymbolAddress((void**)&pK, g_K);
    cudaGetSymbolAddress((void**)&pV, g_V);
    cudaGetSymbolAddress((void**)&pC, g_C);

    dim3 ggrid(DIM / BN, MROWS / BM);     // (8, 64)
    gemm_tf32<<<ggrid, 256>>>(x, WQ, pQ, MROWS, DIM, DIM);
    gemm_tf32<<<ggrid, 256>>>(x, WK, pK, MROWS, DIM, DIM);
    gemm_tf32<<<ggrid, 256>>>(x, WV, pV, MROWS, DIM, DIM);

    dim3 agrid(SEQ / AQ, HEADS, BATCH);   // (32, 16, 4)
    attn_mma<<<agrid, 128>>>(pQ, pK, pV, pC);

    gemm_tf32<<<ggrid, 256>>>(pC, WO, out, MROWS, DIM, DIM);
}

// round 17
// speedup vs baseline: 4.1950x; 1.0317x over previous
#include <cuda_runtime.h>
#include <cuda_bf16.h>
#include <cstddef>
#include <cstdint>

// Problem constants
#define BATCH 4
#define SEQ   2048
#define DIM   1024
#define HEADS 16
#define DH    64
#define MROWS (BATCH*SEQ)  // 8192
#define SCALE 0.03125f     // 1/sqrt(1024)

// Scratch (allocation-free rule: __device__ globals)
__device__ float g_Q[(size_t)MROWS * DIM];
__device__ float g_K[(size_t)MROWS * DIM];
__device__ float g_V[(size_t)MROWS * DIM];
__device__ float g_C[(size_t)MROWS * DIM];

__device__ __forceinline__ float to_tf32(float x) {
    float r;
    asm("cvt.rna.tf32.f32 %0, %1;" : "=f"(r) : "f"(x));
    return r;
}

__device__ __forceinline__ void mma_tf32(float* c, const uint32_t* a, const uint32_t* b) {
    asm volatile(
        "mma.sync.aligned.m16n8k8.row.col.f32.tf32.tf32.f32 "
        "{%0,%1,%2,%3}, {%4,%5,%6,%7}, {%8,%9}, {%0,%1,%2,%3};"
        : "+f"(c[0]), "+f"(c[1]), "+f"(c[2]), "+f"(c[3])
        : "r"(a[0]), "r"(a[1]), "r"(a[2]), "r"(a[3]), "r"(b[0]), "r"(b[1]));
}

__device__ __forceinline__ uint32_t smem_u32(const void* p) {
    uint32_t a;
    asm("{ .reg .u64 t; cvta.to.shared.u64 t, %1; cvt.u32.u64 %0, t; }"
        : "=r"(a) : "l"(p));
    return a;
}

__device__ __forceinline__ void cp_async16(void* smem, const void* gmem) {
    asm volatile("cp.async.cg.shared.global [%0], [%1], 16;"
                 :: "r"(smem_u32(smem)), "l"(gmem) : "memory");
}
#define CP_COMMIT() asm volatile("cp.async.commit_group;" ::: "memory")
#define CP_WAIT0()  asm volatile("cp.async.wait_group 0;" ::: "memory")

// ---------------------------------------------------------------------------
// TF32 mma.sync GEMM body, 2-stage smem double buffer (cvt.rna preserved).
// C[M,N] = A[M,K] * B[K,N]; 128x128x16 tile, 256 threads, warp tile 32x64.
// ---------------------------------------------------------------------------
#define BM 128
#define BN 128
#define BK 16
#define SA_STR 20
#define SB_STR 136

struct GemmSmem {
    float sA[2][BM * SA_STR];
    float sB[2][BK * SB_STR];
};

__device__ __forceinline__ void gemm_body(const float* __restrict__ A,
                                          const float* __restrict__ B,
                                          float* __restrict__ C,
                                          int M, int N, int K,
                                          GemmSmem& sm) {
    int tid  = threadIdx.x;
    int lane = tid & 31;
    int warp = tid >> 5;
    int gr = lane >> 2;
    int tq = lane & 3;
    int wm = (warp & 3) * 32;
    int wn = (warp >> 2) * 64;

    int bx = blockIdx.x, by = blockIdx.y;

    int a_row1 = tid >> 2;
    int a_kc   = (tid & 3) * 4;
    int b_kr   = tid >> 5;
    int b_nc   = (tid & 31) * 4;

    const float* Ap = A + (size_t)(by * BM + a_row1) * K + a_kc;
    const float* Bp = B + (size_t)b_kr * N + bx * BN + b_nc;

    float acc[2][8][4];
#pragma unroll
    for (int mt = 0; mt < 2; mt++)
#pragma unroll
        for (int nt = 0; nt < 8; nt++)
#pragma unroll
            for (int i = 0; i < 4; i++) acc[mt][nt][i] = 0.f;

    float4 ra0 = *(const float4*)(Ap);
    float4 ra1 = *(const float4*)(Ap + (size_t)64 * K);
    float4 rb0 = *(const float4*)(Bp);
    float4 rb1 = *(const float4*)(Bp + (size_t)8 * N);
    {
        float4 t;
        t.x = to_tf32(ra0.x); t.y = to_tf32(ra0.y); t.z = to_tf32(ra0.z); t.w = to_tf32(ra0.w);
        *(float4*)&sm.sA[0][a_row1 * SA_STR + a_kc] = t;
        t.x = to_tf32(ra1.x); t.y = to_tf32(ra1.y); t.z = to_tf32(ra1.z); t.w = to_tf32(ra1.w);
        *(float4*)&sm.sA[0][(a_row1 + 64) * SA_STR + a_kc] = t;
        t.x = to_tf32(rb0.x); t.y = to_tf32(rb0.y); t.z = to_tf32(rb0.z); t.w = to_tf32(rb0.w);
        *(float4*)&sm.sB[0][b_kr * SB_STR + b_nc] = t;
        t.x = to_tf32(rb1.x); t.y = to_tf32(rb1.y); t.z = to_tf32(rb1.z); t.w = to_tf32(rb1.w);
        *(float4*)&sm.sB[0][(b_kr + 8) * SB_STR + b_nc] = t;
    }
    __syncthreads();

    const int NIT = K / BK;
    for (int it = 0; it < NIT; it++) {
        const int cb = it & 1;

        if (it + 1 < NIT) {
            Ap += BK;
            Bp += (size_t)BK * N;
            ra0 = *(const float4*)(Ap);
            ra1 = *(const float4*)(Ap + (size_t)64 * K);
            rb0 = *(const float4*)(Bp);
            rb1 = *(const float4*)(Bp + (size_t)8 * N);
        }

#pragma unroll
        for (int kt = 0; kt < BK; kt += 8) {
            uint32_t af[2][4];
            uint32_t bf[8][2];
#pragma unroll
            for (int mt = 0; mt < 2; mt++) {
                int base = (wm + mt * 16 + gr) * SA_STR + kt + tq;
                af[mt][0] = __float_as_uint(sm.sA[cb][base]);
                af[mt][1] = __float_as_uint(sm.sA[cb][base + 8 * SA_STR]);
                af[mt][2] = __float_as_uint(sm.sA[cb][base + 4]);
                af[mt][3] = __float_as_uint(sm.sA[cb][base + 8 * SA_STR + 4]);
            }
#pragma unroll
            for (int nt = 0; nt < 8; nt++) {
                int nb = wn + nt * 8 + gr;
                bf[nt][0] = __float_as_uint(sm.sB[cb][(kt + tq) * SB_STR + nb]);
                bf[nt][1] = __float_as_uint(sm.sB[cb][(kt + tq + 4) * SB_STR + nb]);
            }
#pragma unroll
            for (int mt = 0; mt < 2; mt++)
#pragma unroll
                for (int nt = 0; nt < 8; nt++)
                    mma_tf32(acc[mt][nt], af[mt], bf[nt]);
        }

        if (it + 1 < NIT) {
            const int nb = (it + 1) & 1;
            float4 t;
            t.x = to_tf32(ra0.x); t.y = to_tf32(ra0.y); t.z = to_tf32(ra0.z); t.w = to_tf32(ra0.w);
            *(float4*)&sm.sA[nb][a_row1 * SA_STR + a_kc] = t;
            t.x = to_tf32(ra1.x); t.y = to_tf32(ra1.y); t.z = to_tf32(ra1.z); t.w = to_tf32(ra1.w);
            *(float4*)&sm.sA[nb][(a_row1 + 64) * SA_STR + a_kc] = t;
            t.x = to_tf32(rb0.x); t.y = to_tf32(rb0.y); t.z = to_tf32(rb0.z); t.w = to_tf32(rb0.w);
            *(float4*)&sm.sB[nb][b_kr * SB_STR + b_nc] = t;
            t.x = to_tf32(rb1.x); t.y = to_tf32(rb1.y); t.z = to_tf32(rb1.z); t.w = to_tf32(rb1.w);
            *(float4*)&sm.sB[nb][(b_kr + 8) * SB_STR + b_nc] = t;
            __syncthreads();
        }
    }

#pragma unroll
    for (int mt = 0; mt < 2; mt++) {
#pragma unroll
        for (int nt = 0; nt < 8; nt++) {
            int row = by * BM + wm + mt * 16 + gr;
            int col = bx * BN + wn + nt * 8 + 2 * tq;
            *(float2*)&C[(size_t)row * N + col] =
                make_float2(acc[mt][nt][0], acc[mt][nt][1]);
            *(float2*)&C[(size_t)(row + 8) * N + col] =
                make_float2(acc[mt][nt][2], acc[mt][nt][3]);
        }
    }
}

// Single GEMM (output projection)
__global__ __launch_bounds__(256) void gemm_tf32(const float* __restrict__ A,
                                                 const float* __restrict__ B,
                                                 float* __restrict__ C,
                                                 int M, int N, int K) {
    __shared__ GemmSmem sm;
    gemm_body(A, B, C, M, N, K, sm);
}

// Fused QKV: grid.z in {0,1,2} selects weight/output. One launch, 1536 CTAs.
__global__ __launch_bounds__(256) void gemm_qkv(const float* __restrict__ A,
                                                const float* __restrict__ W0,
                                                const float* __restrict__ W1,
                                                const float* __restrict__ W2,
                                                float* __restrict__ C0,
                                                float* __restrict__ C1,
                                                float* __restrict__ C2,
                                                int M, int N, int K) {
    __shared__ GemmSmem sm;
    const int z = blockIdx.z;
    const float* B = (z == 0) ? W0 : (z == 1) ? W1 : W2;
    float*       C = (z == 0) ? C0 : (z == 1) ? C1 : C2;
    gemm_body(A, B, C, M, N, K, sm);
}

// ---------------------------------------------------------------------------
// FlashAttention-2 on tf32 mma.sync with 2-stage cp.async K/V pipeline.
// launch_bounds (128,5): force regs<=102 for 5 CTAs/SM (smem 45KB*5=225<=228KB)
// ---------------------------------------------------------------------------
#define AQ 64
#define AK 32
#define KPAD 68
#define VPAD 72
#define PPAD 36

__global__ __launch_bounds__(128, 5) void attn_mma(const float* __restrict__ Q,
                                                   const float* __restrict__ K,
                                                   const float* __restrict__ V,
                                                   float* __restrict__ O) {
    __shared__ float sK[2][AK][KPAD];
    __shared__ float sV[2][AK][VPAD];
    __shared__ float sP[AQ][PPAD];

    const int b = blockIdx.z;
    const int h = blockIdx.y;
    const int qbase = blockIdx.x * AQ;
    const int tid  = threadIdx.x;
    const int warp = tid >> 5;
    const int lane = tid & 31;
    const int gr = lane >> 2;
    const int tq = lane & 3;

    const size_t hbase = (size_t)b * SEQ * DIM + (size_t)h * DH;

    const int srow = tid >> 4;
    const int sc4  = tid & 15;

    uint32_t qf[8][4];
    {
        const int r0 = qbase + warp * 16 + gr;
        const float* q0 = Q + hbase + (size_t)r0 * DIM;
        const float* q1 = Q + hbase + (size_t)(r0 + 8) * DIM;
#pragma unroll
        for (int ks = 0; ks < 8; ks++) {
            qf[ks][0] = __float_as_uint(to_tf32(SCALE * q0[ks * 8 + tq]));
            qf[ks][1] = __float_as_uint(to_tf32(SCALE * q1[ks * 8 + tq]));
            qf[ks][2] = __float_as_uint(to_tf32(SCALE * q0[ks * 8 + tq + 4]));
            qf[ks][3] = __float_as_uint(to_tf32(SCALE * q1[ks * 8 + tq + 4]));
        }
    }

    float oA[8][4];
#pragma unroll
    for (int nt = 0; nt < 8; nt++)
#pragma unroll
        for (int i = 0; i < 4; i++) oA[nt][i] = 0.f;

    float m0 = -1e30f, m1 = -1e30f, l0 = 0.f, l1 = 0.f;

#pragma unroll
    for (int i = 0; i < 4; i++) {
        const int row = srow + i * 8;
        cp_async16(&sK[0][row][sc4 * 4], K + hbase + (size_t)row * DIM + sc4 * 4);
        cp_async16(&sV[0][row][sc4 * 4], V + hbase + (size_t)row * DIM + sc4 * 4);
    }
    CP_COMMIT();

    const int NIT = SEQ / AK;   // 64
    for (int it = 0; it < NIT; it++) {
        CP_WAIT0();
        __syncthreads();

        if (it + 1 < NIT) {
            const int nbuf = (it + 1) & 1;
            const size_t tb = hbase + (size_t)(it + 1) * AK * DIM;
#pragma unroll
            for (int i = 0; i < 4; i++) {
                const int row = srow + i * 8;
                cp_async16(&sK[nbuf][row][sc4 * 4], K + tb + (size_t)row * DIM + sc4 * 4);
                cp_async16(&sV[nbuf][row][sc4 * 4], V + tb + (size_t)row * DIM + sc4 * 4);
            }
            CP_COMMIT();
        }

        const int cb = it & 1;

        float sacc[4][4];
#pragma unroll
        for (int nt = 0; nt < 4; nt++)
#pragma unroll
            for (int i = 0; i < 4; i++) sacc[nt][i] = 0.f;

#pragma unroll
        for (int ks = 0; ks < 8; ks++) {
#pragma unroll
            for (int nt = 0; nt < 4; nt++) {
                uint32_t bf[2];
                bf[0] = __float_as_uint(sK[cb][nt * 8 + gr][ks * 8 + tq]);
                bf[1] = __float_as_uint(sK[cb][nt * 8 + gr][ks * 8 + tq + 4]);
                mma_tf32(sacc[nt], qf[ks], bf);
            }
        }

        float tm0 = fmaxf(fmaxf(sacc[0][0], sacc[0][1]), fmaxf(sacc[1][0], sacc[1][1]));
        tm0 = fmaxf(tm0, fmaxf(fmaxf(sacc[2][0], sacc[2][1]), fmaxf(sacc[3][0], sacc[3][1])));
        float tm1 = fmaxf(fmaxf(sacc[0][2], sacc[0][3]), fmaxf(sacc[1][2], sacc[1][3]));
        tm1 = fmaxf(tm1, fmaxf(fmaxf(sacc[2][2], sacc[2][3]), fmaxf(sacc[3][2], sacc[3][3])));
        tm0 = fmaxf(tm0, __shfl_xor_sync(0xffffffffu, tm0, 1));
        tm0 = fmaxf(tm0, __shfl_xor_sync(0xffffffffu, tm0, 2));
        tm1 = fmaxf(tm1, __shfl_xor_sync(0xffffffffu, tm1, 1));
        tm1 = fmaxf(tm1, __shfl_xor_sync(0xffffffffu, tm1, 2));

        const float nm0 = fmaxf(m0, tm0);
        const float nm1 = fmaxf(m1, tm1);
        const float corr0 = __expf(m0 - nm0);
        const float corr1 = __expf(m1 - nm1);
        m0 = nm0; m1 = nm1;

        float rs0 = 0.f, rs1 = 0.f;
        const int pr0 = warp * 16 + gr;
#pragma unroll
        for (int nt = 0; nt < 4; nt++) {
            float p0 = __expf(sacc[nt][0] - nm0);
            float p1 = __expf(sacc[nt][1] - nm0);
            float p2 = __expf(sacc[nt][2] - nm1);
            float p3 = __expf(sacc[nt][3] - nm1);
            rs0 += p0 + p1;
            rs1 += p2 + p3;
            *(float2*)&sP[pr0][nt * 8 + 2 * tq]     = make_float2(to_tf32(p0), to_tf32(p1));
            *(float2*)&sP[pr0 + 8][nt * 8 + 2 * tq] = make_float2(to_tf32(p2), to_tf32(p3));
        }
        rs0 += __shfl_xor_sync(0xffffffffu, rs0, 1);
        rs0 += __shfl_xor_sync(0xffffffffu, rs0, 2);
        rs1 += __shfl_xor_sync(0xffffffffu, rs1, 1);
        rs1 += __shfl_xor_sync(0xffffffffu, rs1, 2);
        l0 = l0 * corr0 + rs0;
        l1 = l1 * corr1 + rs1;

#pragma unroll
        for (int nt = 0; nt < 8; nt++) {
            oA[nt][0] *= corr0; oA[nt][1] *= corr0;
            oA[nt][2] *= corr1; oA[nt][3] *= corr1;
        }
        __syncwarp();

#pragma unroll
        for (int ks = 0; ks < 4; ks++) {
            uint32_t pf[4];
            pf[0] = __float_as_uint(sP[pr0][ks * 8 + tq]);
            pf[1] = __float_as_uint(sP[pr0 + 8][ks * 8 + tq]);
            pf[2] = __float_as_uint(sP[pr0][ks * 8 + tq + 4]);
            pf[3] = __float_as_uint(sP[pr0 + 8][ks * 8 + tq + 4]);
#pragma unroll
            for (int nt = 0; nt < 8; nt++) {
                uint32_t bf[2];
                bf[0] = __float_as_uint(sV[cb][ks * 8 + tq][nt * 8 + gr]);
                bf[1] = __float_as_uint(sV[cb][ks * 8 + tq + 4][nt * 8 + gr]);
                mma_tf32(oA[nt], pf, bf);
            }
        }
    }

    const float inv0 = 1.f / l0;
    const float inv1 = 1.f / l1;
    const int r0 = qbase + warp * 16 + gr;
#pragma unroll
    for (int nt = 0; nt < 8; nt++) {
        const int col = nt * 8 + 2 * tq;
        *(float2*)&O[hbase + (size_t)r0 * DIM + col] =
            make_float2(oA[nt][0] * inv0, oA[nt][1] * inv0);
        *(float2*)&O[hbase + (size_t)(r0 + 8) * DIM + col] =
            make_float2(oA[nt][2] * inv1, oA[nt][3] * inv1);
    }
}

// ---------------------------------------------------------------------------
extern "C" void kernel_launch(void* const* d_in, const int* in_sizes, int n_in,
                              void* d_out, int out_size) {
    const float* x  = (const float*)d_in[0];
    const float* WQ = (const float*)d_in[1];
    const float* WK = (const float*)d_in[2];
    const float* WV = (const float*)d_in[3];
    const float* WO = (const float*)d_in[4];
    float* out = (float*)d_out;

    float *pQ, *pK, *pV, *pC;
    cudaGetSymbolAddress((void**)&pQ, g_Q);
    cudaGetSymbolAddress((void**)&pK, g_K);
    cudaGetSymbolAddress((void**)&pV, g_V);
    cudaGetSymbolAddress((void**)&pC, g_C);

    dim3 qkvgrid(DIM / BN, MROWS / BM, 3);   // (8, 64, 3) fused
    gemm_qkv<<<qkvgrid, 256>>>(x, WQ, WK, WV, pQ, pK, pV, MROWS, DIM, DIM);

    dim3 agrid(SEQ / AQ, HEADS, BATCH);      // (32, 16, 4)
    attn_mma<<<agrid, 128>>>(pQ, pK, pV, pC);

    dim3 ggrid(DIM / BN, MROWS / BM);        // (8, 64)
    gemm_tf32<<<ggrid, 256>>>(pC, WO, out, MROWS, DIM, DIM);
}